// round 13
// baseline (speedup 1.0000x reference)
#include <cuda_runtime.h>

#define VTH 0.5f
#define TAU 0.2f

__device__ __forceinline__ float4 lif4(float4 v) {
    float u = v.x;
    float s0 = (u > VTH) ? 1.0f : 0.0f;
    u = TAU * u * (1.0f - s0) + v.y;
    float s1 = (u > VTH) ? 1.0f : 0.0f;
    u = TAU * u * (1.0f - s1) + v.z;
    float s2 = (u > VTH) ? 1.0f : 0.0f;
    u = TAU * u * (1.0f - s2) + v.w;
    float s3 = (u > VTH) ? 1.0f : 0.0f;
    return make_float4(s0, s1, s2, s3);
}

// x: [N, 4] f32, steps innermost. Best measured memory shape: float4 accesses,
// 4 front-batched independent loads per thread (MLP_p1=4), .cs streaming policy
// both directions. This round: 512-thread CTAs (grid halved to 4096) to cut
// CTA-scheduling / prologue overhead at identical per-warp memory shape.
__global__ void __launch_bounds__(512) lif_kernel4(const float4* __restrict__ x,
                                                   float4* __restrict__ out,
                                                   int n4) {
    int base = blockIdx.x * (blockDim.x * 4) + threadIdx.x;
    int i0 = base;
    int i1 = base + blockDim.x;
    int i2 = base + 2 * blockDim.x;
    int i3 = base + 3 * blockDim.x;

    if (i3 < n4) {
        float4 v0 = __ldcs(&x[i0]);
        float4 v1 = __ldcs(&x[i1]);
        float4 v2 = __ldcs(&x[i2]);
        float4 v3 = __ldcs(&x[i3]);
        float4 r0 = lif4(v0);
        float4 r1 = lif4(v1);
        float4 r2 = lif4(v2);
        float4 r3 = lif4(v3);
        __stcs(&out[i0], r0);
        __stcs(&out[i1], r1);
        __stcs(&out[i2], r2);
        __stcs(&out[i3], r3);
    } else {
        if (i0 < n4) __stcs(&out[i0], lif4(__ldcs(&x[i0])));
        if (i1 < n4) __stcs(&out[i1], lif4(__ldcs(&x[i1])));
        if (i2 < n4) __stcs(&out[i2], lif4(__ldcs(&x[i2])));
    }
}

extern "C" void kernel_launch(void* const* d_in, const int* in_sizes, int n_in,
                              void* d_out, int out_size) {
    const float4* x = (const float4*)d_in[0];
    float4* out = (float4*)d_out;
    int n4 = out_size / 4;  // neurons (4 contiguous f32 steps each)

    int threads = 512;
    int per_block = threads * 4;
    int blocks = (n4 + per_block - 1) / per_block;
    lif_kernel4<<<blocks, threads>>>(x, out, n4);
}